// round 1
// baseline (speedup 1.0000x reference)
#include <cuda_runtime.h>
#include <math.h>

#define SL   4096
#define DIM  2048
#define NH   8
#define NKV  2
#define HDIM 256
#define WIN  512
#define KVD  (NKV*HDIM)   // 512

// Scratch (static device globals; no allocation allowed)
__device__ float g_q[SL * DIM];
__device__ float g_k[SL * KVD];
__device__ float g_v[SL * KVD];
__device__ float g_att[SL * DIM];

// ---------------------------------------------------------------------------
// SGEMM: C[M,N] = A[M,K] @ B[K,N], all row-major. M%128==0, N%128==0, K%8==0.
// 128x128 block tile, BK=8, 256 threads, 8x8 per thread (split 4+4).
// ---------------------------------------------------------------------------
__global__ __launch_bounds__(256, 2)
void sgemm128(const float* __restrict__ A, const float* __restrict__ B,
              float* __restrict__ C, int M, int N, int K) {
    __shared__ float As[8][128];   // transposed: As[k][m]
    __shared__ float Bs[8][128];   // Bs[k][n]

    const int tid  = threadIdx.x;
    const int tx   = tid & 15;          // 0..15  -> n fragment
    const int ty   = tid >> 4;          // 0..15  -> m fragment
    const int arow = tid >> 1;          // 0..127
    const int acol = (tid & 1) << 2;    // 0 or 4
    const int brow = tid >> 5;          // 0..7
    const int bcol = (tid & 31) << 2;   // 0..124

    const float* Aptr = A + (blockIdx.y * 128 + arow) * K + acol;
    const float* Bptr = B + brow * N + blockIdx.x * 128 + bcol;

    float acc[2][4][2][4];
    #pragma unroll
    for (int mi = 0; mi < 2; mi++)
        #pragma unroll
        for (int i = 0; i < 4; i++)
            #pragma unroll
            for (int nj = 0; nj < 2; nj++)
                #pragma unroll
                for (int j = 0; j < 4; j++) acc[mi][i][nj][j] = 0.0f;

    float4 av = *(const float4*)(Aptr);
    float4 bv = *(const float4*)(Bptr);

    for (int k0 = 0; k0 < K; k0 += 8) {
        As[acol + 0][arow] = av.x;
        As[acol + 1][arow] = av.y;
        As[acol + 2][arow] = av.z;
        As[acol + 3][arow] = av.w;
        *(float4*)&Bs[brow][bcol] = bv;
        __syncthreads();

        if (k0 + 8 < K) {
            av = *(const float4*)(Aptr + k0 + 8);
            bv = *(const float4*)(Bptr + (k0 + 8) * N);
        }

        #pragma unroll
        for (int kk = 0; kk < 8; kk++) {
            float a[8], b[8];
            *(float4*)&a[0] = *(float4*)&As[kk][ty * 4];
            *(float4*)&a[4] = *(float4*)&As[kk][64 + ty * 4];
            *(float4*)&b[0] = *(float4*)&Bs[kk][tx * 4];
            *(float4*)&b[4] = *(float4*)&Bs[kk][64 + tx * 4];
            #pragma unroll
            for (int mi = 0; mi < 2; mi++)
                #pragma unroll
                for (int i = 0; i < 4; i++)
                    #pragma unroll
                    for (int nj = 0; nj < 2; nj++)
                        #pragma unroll
                        for (int j = 0; j < 4; j++)
                            acc[mi][i][nj][j] += a[mi * 4 + i] * b[nj * 4 + j];
        }
        __syncthreads();
    }

    #pragma unroll
    for (int mi = 0; mi < 2; mi++)
        #pragma unroll
        for (int i = 0; i < 4; i++) {
            int row = blockIdx.y * 128 + mi * 64 + ty * 4 + i;
            #pragma unroll
            for (int nj = 0; nj < 2; nj++) {
                float4 vv = make_float4(acc[mi][i][nj][0], acc[mi][i][nj][1],
                                        acc[mi][i][nj][2], acc[mi][i][nj][3]);
                *(float4*)&C[row * N + blockIdx.x * 128 + nj * 64 + tx * 4] = vv;
            }
        }
}

// ---------------------------------------------------------------------------
// Per-head RMSNorm (+ optional scale) + full-dim RoPE (rope_fraction = 1.0).
// grid = (SL, 12): y 0..7 -> q heads, 8..9 -> k heads, 10..11 -> v heads.
// 128 threads; thread t owns elements t and t+128 (the RoPE pair).
// ---------------------------------------------------------------------------
__global__ void norm_rope_kernel(const int* __restrict__ positions,
                                 const float* __restrict__ q_scale,
                                 const float* __restrict__ k_scale) {
    const int token = blockIdx.x;
    const int which = blockIdx.y;
    float* base;
    const float* scale = nullptr;
    bool do_rope = true;
    if (which < 8)        { base = g_q + token * DIM + which * HDIM;        scale = q_scale; }
    else if (which < 10)  { base = g_k + token * KVD + (which - 8) * HDIM;  scale = k_scale; }
    else                  { base = g_v + token * KVD + (which - 10) * HDIM; do_rope = false; }

    const int t = threadIdx.x;  // 0..127
    float x1 = base[t];
    float x2 = base[t + 128];

    float ss = x1 * x1 + x2 * x2;
    #pragma unroll
    for (int off = 16; off > 0; off >>= 1)
        ss += __shfl_xor_sync(0xffffffffu, ss, off);
    __shared__ float red[4];
    if ((t & 31) == 0) red[t >> 5] = ss;
    __syncthreads();
    ss = red[0] + red[1] + red[2] + red[3];

    float inv = rsqrtf(ss * (1.0f / 256.0f) + 1e-6f);
    x1 *= inv;
    x2 *= inv;
    if (scale) { x1 *= scale[t]; x2 *= scale[t + 128]; }

    if (do_rope) {
        float pos = (float)positions[token];
        float timescale = powf(10000.0f, (float)t * (1.0f / 128.0f));
        float sinu = pos / timescale;
        float sv, cv;
        sincosf(sinu, &sv, &cv);
        base[t]       = x1 * cv - x2 * sv;
        base[t + 128] = x2 * cv + x1 * sv;
    } else {
        base[t]       = x1;
        base[t + 128] = x2;
    }
}

// ---------------------------------------------------------------------------
// Sliding-window causal attention (flash-style, fp32).
// grid = (SL/64, NH). block = 256. One block = (head, 64 query rows).
// Keys streamed in 64-key chunks (window 512 -> at most 9 chunks).
// Thread t: qg = t/16 (4 q rows: 4qg..), tx = t%16.
//   score phase : thread owns S[4q x 4k] (k cols 4tx..)
//   PV phase    : thread owns O[4q x 16d], d = r*64 + 4*tx + c
// SMEM: Qs[d][q] (256x68), Ks[d][k] (256x68), Vs[k][d] (64x256), Ps[k][q] (64x68)
// ---------------------------------------------------------------------------
#define QSTR 68
#define ATT_SMEM ((256*QSTR + 256*QSTR + 64*256 + 64*QSTR) * 4)

__global__ __launch_bounds__(256, 1)
void attn_kernel() {
    extern __shared__ float sm[];
    float* Qs = sm;                     // [256][68]
    float* Ks = Qs + 256 * QSTR;        // [256][68]
    float* Vs = Ks + 256 * QSTR;        // [64][256]
    float* Ps = Vs + 64 * 256;          // [64][68]

    const int tid = threadIdx.x;
    const int tx  = tid & 15;
    const int qg  = tid >> 4;
    const int q0  = blockIdx.x << 6;
    const int h   = blockIdx.y;
    const int kh  = h >> 2;             // rep = 4

    // Load Q tile transposed: Qs[d=tid][q=it]
    {
        const float* qsrc = g_q + (size_t)q0 * DIM + h * HDIM;
        #pragma unroll
        for (int it = 0; it < 64; it += 4) {
            float4 tmp;
            tmp.x = qsrc[(it + 0) * DIM + tid];
            tmp.y = qsrc[(it + 1) * DIM + tid];
            tmp.z = qsrc[(it + 2) * DIM + tid];
            tmp.w = qsrc[(it + 3) * DIM + tid];
            *(float4*)&Qs[tid * QSTR + it] = tmp;
        }
    }

    float o[4][4][4];
    #pragma unroll
    for (int i = 0; i < 4; i++)
        #pragma unroll
        for (int r = 0; r < 4; r++)
            #pragma unroll
            for (int c = 0; c < 4; c++) o[i][r][c] = 0.0f;

    float m_run[4], l_run[4];
    #pragma unroll
    for (int i = 0; i < 4; i++) { m_run[i] = -INFINITY; l_run[i] = 0.0f; }

    const int qb = blockIdx.x;
    const int kb_lo = (qb - 8 > 0) ? (qb - 8) : 0;

    for (int kb = kb_lo; kb <= qb; kb++) {
        const int k0 = kb << 6;
        __syncthreads();  // protect Ks/Vs/Ps from previous chunk's readers

        // Load K chunk transposed: Ks[d=tid][k=it]
        {
            const float* ksrc = g_k + (size_t)k0 * KVD + kh * HDIM;
            #pragma unroll
            for (int it = 0; it < 64; it += 4) {
                float4 tmp;
                tmp.x = ksrc[(it + 0) * KVD + tid];
                tmp.y = ksrc[(it + 1) * KVD + tid];
                tmp.z = ksrc[(it + 2) * KVD + tid];
                tmp.w = ksrc[(it + 3) * KVD + tid];
                *(float4*)&Ks[tid * QSTR + it] = tmp;
            }
        }
        // Load V chunk direct: Vs[k][d]
        {
            const float* vsrc = g_v + (size_t)k0 * KVD + kh * HDIM;
            #pragma unroll
            for (int it = 0; it < 16; it++) {
                int u  = it * 256 + tid;
                int kk = u >> 6;
                int dc = u & 63;
                *(float4*)&Vs[kk * 256 + dc * 4] =
                    *(const float4*)&vsrc[kk * KVD + dc * 4];
            }
        }
        __syncthreads();

        // ---- scores: S = Q_tile @ K_chunk^T ----
        float s[4][4];
        #pragma unroll
        for (int i = 0; i < 4; i++)
            #pragma unroll
            for (int j = 0; j < 4; j++) s[i][j] = 0.0f;

        #pragma unroll 8
        for (int d = 0; d < 256; d++) {
            float a[4], b[4];
            *(float4*)a = *(float4*)&Qs[d * QSTR + qg * 4];
            *(float4*)b = *(float4*)&Ks[d * QSTR + tx * 4];
            #pragma unroll
            for (int i = 0; i < 4; i++)
                #pragma unroll
                for (int j = 0; j < 4; j++)
                    s[i][j] += a[i] * b[j];
        }

        // ---- mask (only boundary chunks need it) ----
        if (kb == qb) {  // causal: j <= q
            #pragma unroll
            for (int i = 0; i < 4; i++)
                #pragma unroll
                for (int j = 0; j < 4; j++)
                    if (k0 + tx * 4 + j > q0 + qg * 4 + i) s[i][j] = -INFINITY;
        }
        if (kb == qb - 8) {  // window: j >= q - (WIN-1)
            #pragma unroll
            for (int i = 0; i < 4; i++)
                #pragma unroll
                for (int j = 0; j < 4; j++)
                    if (k0 + tx * 4 + j < q0 + qg * 4 + i - (WIN - 1)) s[i][j] = -INFINITY;
        }

        // ---- online softmax update ----
        float rowm[4];
        #pragma unroll
        for (int i = 0; i < 4; i++)
            rowm[i] = fmaxf(fmaxf(s[i][0], s[i][1]), fmaxf(s[i][2], s[i][3]));
        #pragma unroll
        for (int off = 1; off < 16; off <<= 1)
            #pragma unroll
            for (int i = 0; i < 4; i++)
                rowm[i] = fmaxf(rowm[i], __shfl_xor_sync(0xffffffffu, rowm[i], off));

        float alpha[4], lc[4];
        #pragma unroll
        for (int i = 0; i < 4; i++) {
            float mn = fmaxf(m_run[i], rowm[i]);
            float msafe = (mn == -INFINITY) ? 0.0f : mn;
            alpha[i] = (mn == -INFINITY) ? 1.0f : __expf(m_run[i] - mn);
            m_run[i] = mn;
            lc[i] = 0.0f;
            #pragma unroll
            for (int j = 0; j < 4; j++) {
                s[i][j] = __expf(s[i][j] - msafe);
                lc[i] += s[i][j];
            }
        }
        #pragma unroll
        for (int off = 1; off < 16; off <<= 1)
            #pragma unroll
            for (int i = 0; i < 4; i++)
                lc[i] += __shfl_xor_sync(0xffffffffu, lc[i], off);
        #pragma unroll
        for (int i = 0; i < 4; i++)
            l_run[i] = l_run[i] * alpha[i] + lc[i];

        // write P transposed: Ps[k][q]
        #pragma unroll
        for (int j = 0; j < 4; j++)
            #pragma unroll
            for (int i = 0; i < 4; i++)
                Ps[(tx * 4 + j) * QSTR + qg * 4 + i] = s[i][j];

        // rescale O accumulators
        #pragma unroll
        for (int i = 0; i < 4; i++)
            #pragma unroll
            for (int r = 0; r < 4; r++)
                #pragma unroll
                for (int c = 0; c < 4; c++)
                    o[i][r][c] *= alpha[i];

        __syncthreads();

        // ---- O += P @ V ----
        #pragma unroll 2
        for (int kk = 0; kk < 64; kk++) {
            float p[4];
            *(float4*)p = *(float4*)&Ps[kk * QSTR + qg * 4];
            #pragma unroll
            for (int r = 0; r < 4; r++) {
                float v[4];
                *(float4*)v = *(float4*)&Vs[kk * 256 + r * 64 + tx * 4];
                #pragma unroll
                for (int i = 0; i < 4; i++)
                    #pragma unroll
                    for (int c = 0; c < 4; c++)
                        o[i][r][c] += p[i] * v[c];
            }
        }
    }

    // ---- epilogue: normalize and write ----
    #pragma unroll
    for (int i = 0; i < 4; i++) {
        float inv = 1.0f / l_run[i];
        int row = q0 + qg * 4 + i;
        #pragma unroll
        for (int r = 0; r < 4; r++) {
            float4 vv = make_float4(o[i][r][0] * inv, o[i][r][1] * inv,
                                    o[i][r][2] * inv, o[i][r][3] * inv);
            *(float4*)&g_att[(size_t)row * DIM + h * HDIM + r * 64 + tx * 4] = vv;
        }
    }
}

// ---------------------------------------------------------------------------
extern "C" void kernel_launch(void* const* d_in, const int* in_sizes, int n_in,
                              void* d_out, int out_size) {
    const float* x         = (const float*)d_in[0];
    const int*   positions = (const int*)d_in[1];
    const float* Wq        = (const float*)d_in[2];
    const float* Wk        = (const float*)d_in[3];
    const float* Wv        = (const float*)d_in[4];
    const float* Wo        = (const float*)d_in[5];
    const float* q_scale   = (const float*)d_in[6];
    const float* k_scale   = (const float*)d_in[7];
    float* out = (float*)d_out;

    float *qp, *kp, *vp, *ap;
    cudaGetSymbolAddress((void**)&qp, g_q);
    cudaGetSymbolAddress((void**)&kp, g_k);
    cudaGetSymbolAddress((void**)&vp, g_v);
    cudaGetSymbolAddress((void**)&ap, g_att);

    // QKV projections
    sgemm128<<<dim3(DIM / 128, SL / 128), 256>>>(x, Wq, qp, SL, DIM, DIM);
    sgemm128<<<dim3(KVD / 128, SL / 128), 256>>>(x, Wk, kp, SL, KVD, DIM);
    sgemm128<<<dim3(KVD / 128, SL / 128), 256>>>(x, Wv, vp, SL, KVD, DIM);

    // RMSNorm + RoPE
    norm_rope_kernel<<<dim3(SL, 12), 128>>>(positions, q_scale, k_scale);

    // Attention
    cudaFuncSetAttribute(attn_kernel, cudaFuncAttributeMaxDynamicSharedMemorySize, ATT_SMEM);
    attn_kernel<<<dim3(SL / 64, NH), 256, ATT_SMEM>>>();

    // Output projection
    sgemm128<<<dim3(DIM / 128, SL / 128), 256>>>(ap, Wo, out, SL, DIM, DIM);
}

// round 5
// speedup vs baseline: 1.7639x; 1.7639x over previous
#include <cuda_runtime.h>
#include <cuda_bf16.h>
#include <math.h>
#include <stdint.h>

#define SL   4096
#define DIM  2048
#define NH   8
#define NKV  2
#define HDIM 256
#define WIN  512
#define KVD  (NKV*HDIM)   // 512
#define KVS  1024         // packed K|V row stride

// ---------------- scratch ----------------
__device__ float g_q[SL * DIM];
__device__ float g_kv[SL * KVS];          // [:,0:512]=K, [:,512:1024]=V
__device__ float g_att[SL * DIM];

__device__ __nv_bfloat16 g_xh[SL * DIM],   g_xl[SL * DIM];
__device__ __nv_bfloat16 g_ah[SL * DIM],   g_al[SL * DIM];
__device__ __nv_bfloat16 g_wqh[DIM * DIM], g_wql[DIM * DIM];
__device__ __nv_bfloat16 g_wkvh[KVS * DIM], g_wkvl[KVS * DIM];
__device__ __nv_bfloat16 g_woh[DIM * DIM], g_wol[DIM * DIM];

__device__ __forceinline__ uint32_t smem_u32(const void* p) {
    uint32_t a;
    asm("{ .reg .u64 t; cvta.to.shared.u64 t, %1; cvt.u32.u64 %0, t; }" : "=r"(a) : "l"(p));
    return a;
}

// ---------------- conversion kernels ----------------
__global__ void split_kernel(const float* __restrict__ src,
                             __nv_bfloat16* __restrict__ hi,
                             __nv_bfloat16* __restrict__ lo, int n4) {
    int i = blockIdx.x * blockDim.x + threadIdx.x;
    if (i >= n4) return;
    float4 v = ((const float4*)src)[i];
    float f[4] = {v.x, v.y, v.z, v.w};
    __nv_bfloat16 h[4], l[4];
    #pragma unroll
    for (int j = 0; j < 4; j++) {
        h[j] = __float2bfloat16(f[j]);
        l[j] = __float2bfloat16(f[j] - __bfloat162float(h[j]));
    }
    __nv_bfloat162* h2 = (__nv_bfloat162*)hi;
    __nv_bfloat162* l2 = (__nv_bfloat162*)lo;
    h2[2 * i + 0] = __halves2bfloat162(h[0], h[1]);
    h2[2 * i + 1] = __halves2bfloat162(h[2], h[3]);
    l2[2 * i + 0] = __halves2bfloat162(l[0], l[1]);
    l2[2 * i + 1] = __halves2bfloat162(l[2], l[3]);
}

// src [K, N] row-major fp32 -> hi/lo [N, K] row-major bf16 (transposed)
__global__ void splitT_kernel(const float* __restrict__ src,
                              __nv_bfloat16* __restrict__ hi,
                              __nv_bfloat16* __restrict__ lo, int K, int N) {
    __shared__ float t[32][33];
    const int tx = threadIdx.x, ty = threadIdx.y;
    const int n0 = blockIdx.x * 32, k0 = blockIdx.y * 32;
    #pragma unroll
    for (int i = 0; i < 32; i += 8)
        t[ty + i][tx] = src[(size_t)(k0 + ty + i) * N + n0 + tx];
    __syncthreads();
    #pragma unroll
    for (int i = 0; i < 32; i += 8) {
        float v = t[tx][ty + i];
        __nv_bfloat16 h = __float2bfloat16(v);
        __nv_bfloat16 l = __float2bfloat16(v - __bfloat162float(h));
        size_t o = (size_t)(n0 + ty + i) * K + k0 + tx;
        hi[o] = h;
        lo[o] = l;
    }
}

// ---------------- mma.sync GEMM ----------------
// C[M,N] = A[M,2048] @ B[N,2048]^T, 3-term bf16 split, fp32 accum.
// Block: 128x128, K-chunk 64, double-buffered cp.async. 256 threads.
#define GBK    64
#define ROWB   144                    // 128B data + 16B pad per row
#define TILESZ (128 * ROWB)           // 18432
#define GSTAGE (4 * TILESZ)           // Ah, Al, Bh, Bl
#define GSMEM  (2 * GSTAGE)           // 147456

__device__ __forceinline__ void cp16(uint32_t dst, const void* src) {
    asm volatile("cp.async.cg.shared.global [%0], [%1], 16;" :: "r"(dst), "l"(src) : "memory");
}

__device__ __forceinline__ void g_load_stage(uint32_t stage,
                                             const __nv_bfloat16* __restrict__ Ah,
                                             const __nv_bfloat16* __restrict__ Al,
                                             const __nv_bfloat16* __restrict__ Bh,
                                             const __nv_bfloat16* __restrict__ Bl,
                                             int m0, int n0, int kc) {
    const int tid = threadIdx.x;
    const __nv_bfloat16* srcs[4] = {
        Ah + (size_t)m0 * DIM + kc, Al + (size_t)m0 * DIM + kc,
        Bh + (size_t)n0 * DIM + kc, Bl + (size_t)n0 * DIM + kc};
    #pragma unroll
    for (int t = 0; t < 4; t++) {
        #pragma unroll
        for (int i = 0; i < 4; i++) {
            int u = i * 256 + tid;          // 0..1023
            int row = u >> 3;
            int cb  = (u & 7) * 16;         // byte offset in row (0..112)
            const char* s = (const char*)(srcs[t] + (size_t)row * DIM) + cb;
            cp16(stage + t * TILESZ + row * ROWB + cb, s);
        }
    }
}

__device__ __forceinline__ void ldm4(uint32_t a, uint32_t r[4]) {
    asm volatile("ldmatrix.sync.aligned.m8n8.x4.shared.b16 {%0,%1,%2,%3}, [%4];"
                 : "=r"(r[0]), "=r"(r[1]), "=r"(r[2]), "=r"(r[3]) : "r"(a));
}
__device__ __forceinline__ void mma16816(float c[4], const uint32_t a[4], uint32_t b0, uint32_t b1) {
    asm volatile("mma.sync.aligned.m16n8k16.row.col.f32.bf16.bf16.f32 "
                 "{%0,%1,%2,%3}, {%4,%5,%6,%7}, {%8,%9}, {%0,%1,%2,%3};"
                 : "+f"(c[0]), "+f"(c[1]), "+f"(c[2]), "+f"(c[3])
                 : "r"(a[0]), "r"(a[1]), "r"(a[2]), "r"(a[3]), "r"(b0), "r"(b1));
}

__global__ __launch_bounds__(256, 1)
void gemm_mma3(const __nv_bfloat16* __restrict__ Ah, const __nv_bfloat16* __restrict__ Al,
               const __nv_bfloat16* __restrict__ Bh, const __nv_bfloat16* __restrict__ Bl,
               float* __restrict__ C, int Nld) {
    extern __shared__ char smem[];
    const uint32_t sb = smem_u32(smem);
    const int tid  = threadIdx.x;
    const int lane = tid & 31;
    const int w    = tid >> 5;
    const int wm   = (w >> 1) * 32;     // 4 m-warps
    const int wn   = (w & 1) * 64;      // 2 n-warps
    const int m0   = blockIdx.y * 128;
    const int n0   = blockIdx.x * 128;

    // per-lane ldmatrix byte offsets within a tile
    uint32_t a_off[2], b_off[4];
    #pragma unroll
    for (int mi = 0; mi < 2; mi++)
        a_off[mi] = (uint32_t)((wm + mi * 16 + (lane & 15)) * ROWB + ((lane >> 4) << 4));
    #pragma unroll
    for (int ni = 0; ni < 4; ni++)
        b_off[ni] = (uint32_t)((wn + ni * 16 + (lane & 7) + ((lane >> 4) << 3)) * ROWB
                               + (((lane >> 3) & 1) << 4));

    float acc[2][8][4];
    #pragma unroll
    for (int mi = 0; mi < 2; mi++)
        #pragma unroll
        for (int nj = 0; nj < 8; nj++)
            #pragma unroll
            for (int e = 0; e < 4; e++) acc[mi][nj][e] = 0.0f;

    const int nch = DIM / GBK;  // 32

    g_load_stage(sb, Ah, Al, Bh, Bl, m0, n0, 0);
    asm volatile("cp.async.commit_group;" ::: "memory");
    g_load_stage(sb + GSTAGE, Ah, Al, Bh, Bl, m0, n0, GBK);
    asm volatile("cp.async.commit_group;" ::: "memory");

    for (int c = 0; c < nch; c++) {
        if (c == nch - 1) asm volatile("cp.async.wait_group 0;" ::: "memory");
        else              asm volatile("cp.async.wait_group 1;" ::: "memory");
        __syncthreads();

        const uint32_t st  = sb + (uint32_t)(c & 1) * GSTAGE;
        const uint32_t tAh = st;
        const uint32_t tAl = st + TILESZ;
        const uint32_t tBh = st + 2 * TILESZ;
        const uint32_t tBl = st + 3 * TILESZ;

        #pragma unroll
        for (int ks = 0; ks < 4; ks++) {
            const uint32_t kb = (uint32_t)(ks * 32);
            uint32_t ah[2][4], al_[2][4], bh[4][4], bl[4][4];
            #pragma unroll
            for (int mi = 0; mi < 2; mi++) {
                ldm4(tAh + a_off[mi] + kb, ah[mi]);
                ldm4(tAl + a_off[mi] + kb, al_[mi]);
            }
            #pragma unroll
            for (int ni = 0; ni < 4; ni++) {
                ldm4(tBh + b_off[ni] + kb, bh[ni]);
                ldm4(tBl + b_off[ni] + kb, bl[ni]);
            }
            #pragma unroll
            for (int mi = 0; mi < 2; mi++)
                #pragma unroll
                for (int ni = 0; ni < 4; ni++) {
                    // hi*hi
                    mma16816(acc[mi][ni * 2 + 0], ah[mi], bh[ni][0], bh[ni][1]);
                    mma16816(acc[mi][ni * 2 + 1], ah[mi], bh[ni][2], bh[ni][3]);
                    // lo*hi
                    mma16816(acc[mi][ni * 2 + 0], al_[mi], bh[ni][0], bh[ni][1]);
                    mma16816(acc[mi][ni * 2 + 1], al_[mi], bh[ni][2], bh[ni][3]);
                    // hi*lo
                    mma16816(acc[mi][ni * 2 + 0], ah[mi], bl[ni][0], bl[ni][1]);
                    mma16816(acc[mi][ni * 2 + 1], ah[mi], bl[ni][2], bl[ni][3]);
                }
        }
        __syncthreads();
        if (c + 2 < nch) {
            g_load_stage(sb + (uint32_t)(c & 1) * GSTAGE, Ah, Al, Bh, Bl, m0, n0, (c + 2) * GBK);
            asm volatile("cp.async.commit_group;" ::: "memory");
        }
    }

    // epilogue
    const int mrow = m0 + wm + (lane >> 2);
    const int ncol = n0 + wn + (lane & 3) * 2;
    #pragma unroll
    for (int mi = 0; mi < 2; mi++)
        #pragma unroll
        for (int nj = 0; nj < 8; nj++) {
            float* p0 = C + (size_t)(mrow + mi * 16) * Nld + ncol + nj * 8;
            float* p1 = C + (size_t)(mrow + mi * 16 + 8) * Nld + ncol + nj * 8;
            *(float2*)p0 = make_float2(acc[mi][nj][0], acc[mi][nj][1]);
            *(float2*)p1 = make_float2(acc[mi][nj][2], acc[mi][nj][3]);
        }
}

// ---------------- RMSNorm + RoPE ----------------
__global__ void norm_rope_kernel(const int* __restrict__ positions,
                                 const float* __restrict__ q_scale,
                                 const float* __restrict__ k_scale) {
    const int token = blockIdx.x;
    const int which = blockIdx.y;
    float* base;
    const float* scale = nullptr;
    bool do_rope = true;
    if (which < 8)        { base = g_q  + token * DIM + which * HDIM;              scale = q_scale; }
    else if (which < 10)  { base = g_kv + token * KVS + (which - 8) * HDIM;        scale = k_scale; }
    else                  { base = g_kv + token * KVS + 512 + (which - 10) * HDIM; do_rope = false; }

    const int t = threadIdx.x;
    float x1 = base[t];
    float x2 = base[t + 128];

    float ss = x1 * x1 + x2 * x2;
    #pragma unroll
    for (int off = 16; off > 0; off >>= 1)
        ss += __shfl_xor_sync(0xffffffffu, ss, off);
    __shared__ float red[4];
    if ((t & 31) == 0) red[t >> 5] = ss;
    __syncthreads();
    ss = red[0] + red[1] + red[2] + red[3];

    float inv = rsqrtf(ss * (1.0f / 256.0f) + 1e-6f);
    x1 *= inv;
    x2 *= inv;
    if (scale) { x1 *= scale[t]; x2 *= scale[t + 128]; }

    if (do_rope) {
        float pos = (float)positions[token];
        float timescale = powf(10000.0f, (float)t * (1.0f / 128.0f));
        float sinu = pos / timescale;
        float sv, cv;
        sincosf(sinu, &sv, &cv);
        base[t]       = x1 * cv - x2 * sv;
        base[t + 128] = x2 * cv + x1 * sv;
    } else {
        base[t]       = x1;
        base[t + 128] = x2;
    }
}

// ---------------- attention (fp32 flash) ----------------
#define QSTR 68
#define ATT_SMEM ((256*QSTR + 256*QSTR + 64*256 + 64*QSTR) * 4)

__global__ __launch_bounds__(256, 1)
void attn_kernel() {
    extern __shared__ float sm[];
    float* Qs = sm;
    float* Ks = Qs + 256 * QSTR;
    float* Vs = Ks + 256 * QSTR;
    float* Ps = Vs + 64 * 256;

    const int tid = threadIdx.x;
    const int tx  = tid & 15;
    const int qg  = tid >> 4;
    const int q0  = blockIdx.x << 6;
    const int h   = blockIdx.y;
    const int kh  = h >> 2;

    {
        const float* qsrc = g_q + (size_t)q0 * DIM + h * HDIM;
        #pragma unroll
        for (int it = 0; it < 64; it += 4) {
            float4 tmp;
            tmp.x = qsrc[(it + 0) * DIM + tid];
            tmp.y = qsrc[(it + 1) * DIM + tid];
            tmp.z = qsrc[(it + 2) * DIM + tid];
            tmp.w = qsrc[(it + 3) * DIM + tid];
            *(float4*)&Qs[tid * QSTR + it] = tmp;
        }
    }

    float o[4][4][4];
    #pragma unroll
    for (int i = 0; i < 4; i++)
        #pragma unroll
        for (int r = 0; r < 4; r++)
            #pragma unroll
            for (int c = 0; c < 4; c++) o[i][r][c] = 0.0f;

    float m_run[4], l_run[4];
    #pragma unroll
    for (int i = 0; i < 4; i++) { m_run[i] = -INFINITY; l_run[i] = 0.0f; }

    const int qb = blockIdx.x;
    const int kb_lo = (qb - 8 > 0) ? (qb - 8) : 0;

    for (int kb = kb_lo; kb <= qb; kb++) {
        const int k0 = kb << 6;
        __syncthreads();

        {
            const float* ksrc = g_kv + (size_t)k0 * KVS + kh * HDIM;
            #pragma unroll
            for (int it = 0; it < 64; it += 4) {
                float4 tmp;
                tmp.x = ksrc[(it + 0) * KVS + tid];
                tmp.y = ksrc[(it + 1) * KVS + tid];
                tmp.z = ksrc[(it + 2) * KVS + tid];
                tmp.w = ksrc[(it + 3) * KVS + tid];
                *(float4*)&Ks[tid * QSTR + it] = tmp;
            }
        }
        {
            const float* vsrc = g_kv + (size_t)k0 * KVS + 512 + kh * HDIM;
            #pragma unroll
            for (int it = 0; it < 16; it++) {
                int u  = it * 256 + tid;
                int kk = u >> 6;
                int dc = u & 63;
                *(float4*)&Vs[kk * 256 + dc * 4] =
                    *(const float4*)&vsrc[kk * KVS + dc * 4];
            }
        }
        __syncthreads();

        float s[4][4];
        #pragma unroll
        for (int i = 0; i < 4; i++)
            #pragma unroll
            for (int j = 0; j < 4; j++) s[i][j] = 0.0f;

        #pragma unroll 8
        for (int d = 0; d < 256; d++) {
            float a[4], b[4];
            *(float4*)a = *(float4*)&Qs[d * QSTR + qg * 4];
            *(float4*)b = *(float4*)&Ks[d * QSTR + tx * 4];
            #pragma unroll
            for (int i = 0; i < 4; i++)
                #pragma unroll
                for (int j = 0; j < 4; j++)
                    s[i][j] += a[i] * b[j];
        }

        if (kb == qb) {
            #pragma unroll
            for (int i = 0; i < 4; i++)
                #pragma unroll
                for (int j = 0; j < 4; j++)
                    if (k0 + tx * 4 + j > q0 + qg * 4 + i) s[i][j] = -INFINITY;
        }
        if (kb == qb - 8) {
            #pragma unroll
            for (int i = 0; i < 4; i++)
                #pragma unroll
                for (int j = 0; j < 4; j++)
                    if (k0 + tx * 4 + j < q0 + qg * 4 + i - (WIN - 1)) s[i][j] = -INFINITY;
        }

        float rowm[4];
        #pragma unroll
        for (int i = 0; i < 4; i++)
            rowm[i] = fmaxf(fmaxf(s[i][0], s[i][1]), fmaxf(s[i][2], s[i][3]));
        #pragma unroll
        for (int off = 1; off < 16; off <<= 1)
            #pragma unroll
            for (int i = 0; i < 4; i++)
                rowm[i] = fmaxf(rowm[i], __shfl_xor_sync(0xffffffffu, rowm[i], off));

        float alpha[4], lc[4];
        #pragma unroll
        for (int i = 0; i < 4; i++) {
            float mn = fmaxf(m_run[i], rowm[i]);
            float msafe = (mn == -INFINITY) ? 0.0f : mn;
            alpha[i] = (mn == -INFINITY) ? 1.0f : __expf(m_run[i] - mn);
            m_run[i] = mn;
            lc[i] = 0.0f;
            #pragma unroll
            for (int j = 0; j < 4; j++) {
                s[i][j] = __expf(s[i][j] - msafe);
                lc[i] += s[i][j];
            }
        }
        #pragma unroll
        for (int off = 1; off < 16; off <<= 1)
            #pragma unroll
            for (int i = 0; i < 4; i++)
                lc[i] += __shfl_xor_sync(0xffffffffu, lc[i], off);
        #pragma unroll
        for (int i = 0; i < 4; i++)
            l_run[i] = l_run[i] * alpha[i] + lc[i];

        #pragma unroll
        for (int j = 0; j < 4; j++)
            #pragma unroll
            for (int i = 0; i < 4; i++)
                Ps[(tx * 4 + j) * QSTR + qg * 4 + i] = s[i][j];

        #pragma unroll
        for (int i = 0; i < 4; i++)
            #pragma unroll
            for (int r = 0; r < 4; r++)
                #pragma unroll
                for (int c = 0; c < 4; c++)
                    o[i][r][c] *= alpha[i];

        __syncthreads();

        #pragma unroll 2
        for (int kk = 0; kk < 64; kk++) {
            float p[4];
            *(float4*)p = *(float4*)&Ps[kk * QSTR + qg * 4];
            #pragma unroll
            for (int r = 0; r < 4; r++) {
                float v[4];
                *(float4*)v = *(float4*)&Vs[kk * 256 + r * 64 + tx * 4];
                #pragma unroll
                for (int i = 0; i < 4; i++)
                    #pragma unroll
                    for (int c = 0; c < 4; c++)
                        o[i][r][c] += p[i] * v[c];
            }
        }
    }

    #pragma unroll
    for (int i = 0; i < 4; i++) {
        float inv = 1.0f / l_run[i];
        int row = q0 + qg * 4 + i;
        #pragma unroll
        for (int r = 0; r < 4; r++) {
            float4 vv = make_float4(o[i][r][0] * inv, o[i][r][1] * inv,
                                    o[i][r][2] * inv, o[i][r][3] * inv);
            *(float4*)&g_att[(size_t)row * DIM + h * HDIM + r * 64 + tx * 4] = vv;
        }
    }
}

// ---------------------------------------------------------------------------
extern "C" void kernel_launch(void* const* d_in, const int* in_sizes, int n_in,
                              void* d_out, int out_size) {
    const float* x         = (const float*)d_in[0];
    const int*   positions = (const int*)d_in[1];
    const float* Wq        = (const float*)d_in[2];
    const float* Wk        = (const float*)d_in[3];
    const float* Wv        = (const float*)d_in[4];
    const float* Wo        = (const float*)d_in[5];
    const float* q_scale   = (const float*)d_in[6];
    const float* k_scale   = (const float*)d_in[7];
    float* out = (float*)d_out;

    float *qp, *kvp, *ap;
    cudaGetSymbolAddress((void**)&qp,  g_q);
    cudaGetSymbolAddress((void**)&kvp, g_kv);
    cudaGetSymbolAddress((void**)&ap,  g_att);

    __nv_bfloat16 *xh, *xl, *ah, *al, *wqh, *wql, *wkvh, *wkvl, *woh, *wol;
    cudaGetSymbolAddress((void**)&xh, g_xh);     cudaGetSymbolAddress((void**)&xl, g_xl);
    cudaGetSymbolAddress((void**)&ah, g_ah);     cudaGetSymbolAddress((void**)&al, g_al);
    cudaGetSymbolAddress((void**)&wqh, g_wqh);   cudaGetSymbolAddress((void**)&wql, g_wql);
    cudaGetSymbolAddress((void**)&wkvh, g_wkvh); cudaGetSymbolAddress((void**)&wkvl, g_wkvl);
    cudaGetSymbolAddress((void**)&woh, g_woh);   cudaGetSymbolAddress((void**)&wol, g_wol);

    cudaFuncSetAttribute(gemm_mma3, cudaFuncAttributeMaxDynamicSharedMemorySize, GSMEM);
    cudaFuncSetAttribute(attn_kernel, cudaFuncAttributeMaxDynamicSharedMemorySize, ATT_SMEM);

    const int n4 = SL * DIM / 4;

    // split inputs
    split_kernel<<<n4 / 256, 256>>>(x, xh, xl, n4);
    splitT_kernel<<<dim3(DIM / 32, DIM / 32), dim3(32, 8)>>>(Wq, wqh, wql, DIM, DIM);
    splitT_kernel<<<dim3(KVD / 32, DIM / 32), dim3(32, 8)>>>(Wk, wkvh, wkvl, DIM, KVD);
    splitT_kernel<<<dim3(KVD / 32, DIM / 32), dim3(32, 8)>>>(Wv, wkvh + (size_t)KVD * DIM,
                                                             wkvl + (size_t)KVD * DIM, DIM, KVD);
    splitT_kernel<<<dim3(DIM / 32, DIM / 32), dim3(32, 8)>>>(Wo, woh, wol, DIM, DIM);

    // projections on mma.sync
    gemm_mma3<<<dim3(DIM / 128, SL / 128), 256, GSMEM>>>(xh, xl, wqh, wql, qp, DIM);
    gemm_mma3<<<dim3(KVS / 128, SL / 128), 256, GSMEM>>>(xh, xl, wkvh, wkvl, kvp, KVS);

    // RMSNorm + RoPE
    norm_rope_kernel<<<dim3(SL, 12), 128>>>(positions, q_scale, k_scale);

    // Attention
    attn_kernel<<<dim3(SL / 64, NH), 256, ATT_SMEM>>>();

    // Output projection
    split_kernel<<<n4 / 256, 256>>>(ap, ah, al, n4);
    gemm_mma3<<<dim3(DIM / 128, SL / 128), 256, GSMEM>>>(ah, al, woh, wol, out, DIM);
}

// round 8
// speedup vs baseline: 2.3551x; 1.3352x over previous
#include <cuda_runtime.h>
#include <cuda_bf16.h>
#include <math.h>
#include <stdint.h>

#define SL   4096
#define DIM  2048
#define NH   8
#define NKV  2
#define HDIM 256
#define WIN  512
#define KVD  (NKV*HDIM)   // 512
#define KVS  1024         // packed K|V row stride

// ---------------- scratch ----------------
__device__ float g_q[SL * DIM];
__device__ float g_kv[SL * KVS];          // [:,0:512]=K, [:,512:1024]=V (fp32, pre-norm)

__device__ __nv_bfloat16 g_xh[SL * DIM],   g_xl[SL * DIM];     // split x
__device__ __nv_bfloat16 g_qh[SL * DIM],   g_ql[SL * DIM];     // normed+roped Q
__device__ __nv_bfloat16 g_kvh[SL * KVS],  g_kvl[SL * KVS];    // normed K|V
__device__ __nv_bfloat16 g_ah[SL * DIM],   g_al[SL * DIM];     // attention out
__device__ __nv_bfloat16 g_wqh[DIM * DIM], g_wql[DIM * DIM];
__device__ __nv_bfloat16 g_wkvh[KVS * DIM], g_wkvl[KVS * DIM];
__device__ __nv_bfloat16 g_woh[DIM * DIM], g_wol[DIM * DIM];

__device__ __forceinline__ uint32_t smem_u32(const void* p) {
    uint32_t a;
    asm("{ .reg .u64 t; cvta.to.shared.u64 t, %1; cvt.u32.u64 %0, t; }" : "=r"(a) : "l"(p));
    return a;
}
__device__ __forceinline__ void cp16(uint32_t dst, const void* src) {
    asm volatile("cp.async.cg.shared.global [%0], [%1], 16;" :: "r"(dst), "l"(src) : "memory");
}
__device__ __forceinline__ void ldm4(uint32_t a, uint32_t r[4]) {
    asm volatile("ldmatrix.sync.aligned.m8n8.x4.shared.b16 {%0,%1,%2,%3}, [%4];"
                 : "=r"(r[0]), "=r"(r[1]), "=r"(r[2]), "=r"(r[3]) : "r"(a));
}
__device__ __forceinline__ void ldm4t(uint32_t a, uint32_t r[4]) {
    asm volatile("ldmatrix.sync.aligned.m8n8.x4.trans.shared.b16 {%0,%1,%2,%3}, [%4];"
                 : "=r"(r[0]), "=r"(r[1]), "=r"(r[2]), "=r"(r[3]) : "r"(a));
}
__device__ __forceinline__ void mma16816(float c[4], const uint32_t a[4], uint32_t b0, uint32_t b1) {
    asm volatile("mma.sync.aligned.m16n8k16.row.col.f32.bf16.bf16.f32 "
                 "{%0,%1,%2,%3}, {%4,%5,%6,%7}, {%8,%9}, {%0,%1,%2,%3};"
                 : "+f"(c[0]), "+f"(c[1]), "+f"(c[2]), "+f"(c[3])
                 : "r"(a[0]), "r"(a[1]), "r"(a[2]), "r"(a[3]), "r"(b0), "r"(b1));
}

// ---------------- conversion kernels ----------------
__global__ void split_kernel(const float* __restrict__ src,
                             __nv_bfloat16* __restrict__ hi,
                             __nv_bfloat16* __restrict__ lo, int n4) {
    int i = blockIdx.x * blockDim.x + threadIdx.x;
    if (i >= n4) return;
    float4 v = ((const float4*)src)[i];
    float f[4] = {v.x, v.y, v.z, v.w};
    __nv_bfloat16 h[4], l[4];
    #pragma unroll
    for (int j = 0; j < 4; j++) {
        h[j] = __float2bfloat16(f[j]);
        l[j] = __float2bfloat16(f[j] - __bfloat162float(h[j]));
    }
    __nv_bfloat162* h2 = (__nv_bfloat162*)hi;
    __nv_bfloat162* l2 = (__nv_bfloat162*)lo;
    h2[2 * i + 0] = __halves2bfloat162(h[0], h[1]);
    h2[2 * i + 1] = __halves2bfloat162(h[2], h[3]);
    l2[2 * i + 0] = __halves2bfloat162(l[0], l[1]);
    l2[2 * i + 1] = __halves2bfloat162(l[2], l[3]);
}

// src [K, N] row-major fp32 -> hi/lo [N, K] row-major bf16 (transposed)
__global__ void splitT_kernel(const float* __restrict__ src,
                              __nv_bfloat16* __restrict__ hi,
                              __nv_bfloat16* __restrict__ lo, int K, int N) {
    __shared__ float t[32][33];
    const int tx = threadIdx.x, ty = threadIdx.y;
    const int n0 = blockIdx.x * 32, k0 = blockIdx.y * 32;
    #pragma unroll
    for (int i = 0; i < 32; i += 8)
        t[ty + i][tx] = src[(size_t)(k0 + ty + i) * N + n0 + tx];
    __syncthreads();
    #pragma unroll
    for (int i = 0; i < 32; i += 8) {
        float v = t[tx][ty + i];
        __nv_bfloat16 h = __float2bfloat16(v);
        __nv_bfloat16 l = __float2bfloat16(v - __bfloat162float(h));
        size_t o = (size_t)(n0 + ty + i) * K + k0 + tx;
        hi[o] = h;
        lo[o] = l;
    }
}

// ---------------- mma.sync GEMM (unchanged) ----------------
#define GBK    64
#define ROWB   144
#define TILESZ (128 * ROWB)
#define GSTAGE (4 * TILESZ)
#define GSMEM  (2 * GSTAGE)

__device__ __forceinline__ void g_load_stage(uint32_t stage,
                                             const __nv_bfloat16* __restrict__ Ah,
                                             const __nv_bfloat16* __restrict__ Al,
                                             const __nv_bfloat16* __restrict__ Bh,
                                             const __nv_bfloat16* __restrict__ Bl,
                                             int m0, int n0, int kc) {
    const int tid = threadIdx.x;
    const __nv_bfloat16* srcs[4] = {
        Ah + (size_t)m0 * DIM + kc, Al + (size_t)m0 * DIM + kc,
        Bh + (size_t)n0 * DIM + kc, Bl + (size_t)n0 * DIM + kc};
    #pragma unroll
    for (int t = 0; t < 4; t++) {
        #pragma unroll
        for (int i = 0; i < 4; i++) {
            int u = i * 256 + tid;
            int row = u >> 3;
            int cb  = (u & 7) * 16;
            const char* s = (const char*)(srcs[t] + (size_t)row * DIM) + cb;
            cp16(stage + t * TILESZ + row * ROWB + cb, s);
        }
    }
}

__global__ __launch_bounds__(256, 1)
void gemm_mma3(const __nv_bfloat16* __restrict__ Ah, const __nv_bfloat16* __restrict__ Al,
               const __nv_bfloat16* __restrict__ Bh, const __nv_bfloat16* __restrict__ Bl,
               float* __restrict__ C, int Nld) {
    extern __shared__ char smem[];
    const uint32_t sb = smem_u32(smem);
    const int tid  = threadIdx.x;
    const int lane = tid & 31;
    const int w    = tid >> 5;
    const int wm   = (w >> 1) * 32;
    const int wn   = (w & 1) * 64;
    const int m0   = blockIdx.y * 128;
    const int n0   = blockIdx.x * 128;

    uint32_t a_off[2], b_off[4];
    #pragma unroll
    for (int mi = 0; mi < 2; mi++)
        a_off[mi] = (uint32_t)((wm + mi * 16 + (lane & 15)) * ROWB + ((lane >> 4) << 4));
    #pragma unroll
    for (int ni = 0; ni < 4; ni++)
        b_off[ni] = (uint32_t)((wn + ni * 16 + (lane & 7) + ((lane >> 4) << 3)) * ROWB
                               + (((lane >> 3) & 1) << 4));

    float acc[2][8][4];
    #pragma unroll
    for (int mi = 0; mi < 2; mi++)
        #pragma unroll
        for (int nj = 0; nj < 8; nj++)
            #pragma unroll
            for (int e = 0; e < 4; e++) acc[mi][nj][e] = 0.0f;

    const int nch = DIM / GBK;

    g_load_stage(sb, Ah, Al, Bh, Bl, m0, n0, 0);
    asm volatile("cp.async.commit_group;" ::: "memory");
    g_load_stage(sb + GSTAGE, Ah, Al, Bh, Bl, m0, n0, GBK);
    asm volatile("cp.async.commit_group;" ::: "memory");

    for (int c = 0; c < nch; c++) {
        if (c == nch - 1) asm volatile("cp.async.wait_group 0;" ::: "memory");
        else              asm volatile("cp.async.wait_group 1;" ::: "memory");
        __syncthreads();

        const uint32_t st  = sb + (uint32_t)(c & 1) * GSTAGE;
        const uint32_t tAh = st;
        const uint32_t tAl = st + TILESZ;
        const uint32_t tBh = st + 2 * TILESZ;
        const uint32_t tBl = st + 3 * TILESZ;

        #pragma unroll
        for (int ks = 0; ks < 4; ks++) {
            const uint32_t kb = (uint32_t)(ks * 32);
            uint32_t ah[2][4], al_[2][4], bh[4][4], bl[4][4];
            #pragma unroll
            for (int mi = 0; mi < 2; mi++) {
                ldm4(tAh + a_off[mi] + kb, ah[mi]);
                ldm4(tAl + a_off[mi] + kb, al_[mi]);
            }
            #pragma unroll
            for (int ni = 0; ni < 4; ni++) {
                ldm4(tBh + b_off[ni] + kb, bh[ni]);
                ldm4(tBl + b_off[ni] + kb, bl[ni]);
            }
            #pragma unroll
            for (int mi = 0; mi < 2; mi++)
                #pragma unroll
                for (int ni = 0; ni < 4; ni++) {
                    mma16816(acc[mi][ni * 2 + 0], ah[mi], bh[ni][0], bh[ni][1]);
                    mma16816(acc[mi][ni * 2 + 1], ah[mi], bh[ni][2], bh[ni][3]);
                    mma16816(acc[mi][ni * 2 + 0], al_[mi], bh[ni][0], bh[ni][1]);
                    mma16816(acc[mi][ni * 2 + 1], al_[mi], bh[ni][2], bh[ni][3]);
                    mma16816(acc[mi][ni * 2 + 0], ah[mi], bl[ni][0], bl[ni][1]);
                    mma16816(acc[mi][ni * 2 + 1], ah[mi], bl[ni][2], bl[ni][3]);
                }
        }
        __syncthreads();
        if (c + 2 < nch) {
            g_load_stage(sb + (uint32_t)(c & 1) * GSTAGE, Ah, Al, Bh, Bl, m0, n0, (c + 2) * GBK);
            asm volatile("cp.async.commit_group;" ::: "memory");
        }
    }

    const int mrow = m0 + wm + (lane >> 2);
    const int ncol = n0 + wn + (lane & 3) * 2;
    #pragma unroll
    for (int mi = 0; mi < 2; mi++)
        #pragma unroll
        for (int nj = 0; nj < 8; nj++) {
            float* p0 = C + (size_t)(mrow + mi * 16) * Nld + ncol + nj * 8;
            float* p1 = C + (size_t)(mrow + mi * 16 + 8) * Nld + ncol + nj * 8;
            *(float2*)p0 = make_float2(acc[mi][nj][0], acc[mi][nj][1]);
            *(float2*)p1 = make_float2(acc[mi][nj][2], acc[mi][nj][3]);
        }
}

// ---------------- RMSNorm + RoPE -> bf16 hi/lo ----------------
__global__ void norm_rope_kernel(const int* __restrict__ positions,
                                 const float* __restrict__ q_scale,
                                 const float* __restrict__ k_scale) {
    const int token = blockIdx.x;
    const int which = blockIdx.y;
    const float* base;
    __nv_bfloat16 *oh, *ol;
    const float* scale = nullptr;
    bool do_rope = true;
    if (which < 8) {
        size_t off = (size_t)token * DIM + which * HDIM;
        base = g_q + off; oh = g_qh + off; ol = g_ql + off; scale = q_scale;
    } else if (which < 10) {
        size_t off = (size_t)token * KVS + (which - 8) * HDIM;
        base = g_kv + off; oh = g_kvh + off; ol = g_kvl + off; scale = k_scale;
    } else {
        size_t off = (size_t)token * KVS + 512 + (which - 10) * HDIM;
        base = g_kv + off; oh = g_kvh + off; ol = g_kvl + off; do_rope = false;
    }

    const int t = threadIdx.x;
    float x1 = base[t];
    float x2 = base[t + 128];

    float ss = x1 * x1 + x2 * x2;
    #pragma unroll
    for (int off = 16; off > 0; off >>= 1)
        ss += __shfl_xor_sync(0xffffffffu, ss, off);
    __shared__ float red[4];
    if ((t & 31) == 0) red[t >> 5] = ss;
    __syncthreads();
    ss = red[0] + red[1] + red[2] + red[3];

    float inv = rsqrtf(ss * (1.0f / 256.0f) + 1e-6f);
    x1 *= inv;
    x2 *= inv;
    if (scale) { x1 *= scale[t]; x2 *= scale[t + 128]; }

    float y1, y2;
    if (do_rope) {
        float pos = (float)positions[token];
        float timescale = powf(10000.0f, (float)t * (1.0f / 128.0f));
        float sinu = pos / timescale;
        float sv, cv;
        sincosf(sinu, &sv, &cv);
        y1 = x1 * cv - x2 * sv;
        y2 = x2 * cv + x1 * sv;
    } else {
        y1 = x1; y2 = x2;
    }
    __nv_bfloat16 h1 = __float2bfloat16(y1);
    __nv_bfloat16 h2 = __float2bfloat16(y2);
    oh[t]       = h1;  ol[t]       = __float2bfloat16(y1 - __bfloat162float(h1));
    oh[t + 128] = h2;  ol[t + 128] = __float2bfloat16(y2 - __bfloat162float(h2));
}

// ---------------- tensor-core sliding-window attention ----------------
// 64 q x 64 k tiles, HD=256, 3-term bf16 splits, mma.sync.
// warps: wm = w&3 (m16 rows each), wn = w>>2 (2 n-warps).
#define SWZ(row, colb) ((uint32_t)((row) * 512 + ((colb) ^ (((row) & 7) << 4))))
#define O_QH 0
#define O_QL 32768
#define O_KH 65536
#define O_KL 98304
#define O_VH 131072
#define O_VL 163840
#define O_PH 196608
#define O_PL (O_PH + 9216)
#define O_SM (O_PL + 9216)
#define O_SLN (O_SM + 256)
#define O_RM (O_SLN + 256)
#define O_RS (O_RM + 512)
#define ATT2_SMEM (O_RS + 512)
#define MASKV (-10000.0f)

__global__ __launch_bounds__(256, 1)
void attn_mma() {
    extern __shared__ char smem[];
    const uint32_t sb = smem_u32(smem);
    const int tid = threadIdx.x, lane = tid & 31, w = tid >> 5;
    const int wm = w & 3, wn = w >> 2;
    const int qb = blockIdx.x, q0 = qb << 6;
    const int h = blockIdx.y, kh = h >> 2;

    float* sm_m = (float*)(smem + O_SM);
    float* sm_l = (float*)(smem + O_SLN);
    float* red_m = (float*)(smem + O_RM);   // [2][64]
    float* red_s = (float*)(smem + O_RS);   // [2][64]

    if (tid < 64) { sm_m[tid] = MASKV; sm_l[tid] = 0.0f; }

    // load Q hi/lo (once)
    {
        const __nv_bfloat16* qh = g_qh + (size_t)q0 * DIM + h * HDIM;
        const __nv_bfloat16* ql = g_ql + (size_t)q0 * DIM + h * HDIM;
        #pragma unroll
        for (int it = 0; it < 8; it++) {
            int u = it * 256 + tid, row = u >> 5, colb = (u & 31) * 16;
            uint32_t swo = SWZ(row, colb);
            cp16(sb + O_QH + swo, (const char*)(qh + (size_t)row * DIM) + colb);
            cp16(sb + O_QL + swo, (const char*)(ql + (size_t)row * DIM) + colb);
        }
    }
    asm volatile("cp.async.commit_group;" ::: "memory");

    // per-lane geometry
    const int arow  = wm * 16 + (lane & 15);
    const uint32_t acolx = (uint32_t)((lane >> 4) << 4);
    const int r0 = wm * 16 + (lane >> 2);

    float acc_o[16][4];
    #pragma unroll
    for (int nf = 0; nf < 16; nf++)
        #pragma unroll
        for (int e = 0; e < 4; e++) acc_o[nf][e] = 0.0f;

    const int kb_lo = (qb >= 8) ? qb - 8 : 0;

    for (int kb = kb_lo; kb <= qb; kb++) {
        const int k0 = kb << 6;
        __syncthreads();  // prior chunk's smem consumers done

        // load K,V hi/lo for this chunk
        #pragma unroll
        for (int it = 0; it < 8; it++) {
            int u = it * 256 + tid, row = u >> 5, colb = (u & 31) * 16;
            size_t gro = (size_t)(k0 + row) * KVS + kh * HDIM;
            uint32_t swo = SWZ(row, colb);
            cp16(sb + O_KH + swo, (const char*)(g_kvh + gro) + colb);
            cp16(sb + O_KL + swo, (const char*)(g_kvl + gro) + colb);
            cp16(sb + O_VH + swo, (const char*)(g_kvh + gro + 512) + colb);
            cp16(sb + O_VL + swo, (const char*)(g_kvl + gro + 512) + colb);
        }
        asm volatile("cp.async.commit_group;" ::: "memory");
        asm volatile("cp.async.wait_group 0;" ::: "memory");
        __syncthreads();

        // ---- scores: S = Q K^T (3-term) ----
        float s[4][4];
        #pragma unroll
        for (int nf = 0; nf < 4; nf++)
            #pragma unroll
            for (int e = 0; e < 4; e++) s[nf][e] = 0.0f;

        #pragma unroll
        for (int ks = 0; ks < 16; ks++) {
            uint32_t ah[4], al_[4];
            ldm4(sb + O_QH + SWZ(arow, ks * 32 + acolx), ah);
            ldm4(sb + O_QL + SWZ(arow, ks * 32 + acolx), al_);
            #pragma unroll
            for (int ni = 0; ni < 2; ni++) {
                int brow = wn * 32 + ni * 16 + (lane & 7) + ((lane >> 4) << 3);
                uint32_t bcolb = (uint32_t)(ks * 32 + (((lane >> 3) & 1) << 4));
                uint32_t bh[4], bl[4];
                ldm4(sb + O_KH + SWZ(brow, bcolb), bh);
                ldm4(sb + O_KL + SWZ(brow, bcolb), bl);
                mma16816(s[ni * 2 + 0], ah, bh[0], bh[1]);
                mma16816(s[ni * 2 + 1], ah, bh[2], bh[3]);
                mma16816(s[ni * 2 + 0], al_, bh[0], bh[1]);
                mma16816(s[ni * 2 + 1], al_, bh[2], bh[3]);
                mma16816(s[ni * 2 + 0], ah, bl[0], bl[1]);
                mma16816(s[ni * 2 + 1], ah, bl[2], bl[3]);
            }
        }

        // ---- masking ----
        if (kb == qb) {
            #pragma unroll
            for (int nf = 0; nf < 4; nf++) {
                int keyc = k0 + wn * 32 + nf * 8 + (lane & 3) * 2;
                #pragma unroll
                for (int e = 0; e < 2; e++) {
                    if (keyc + e > q0 + r0)     s[nf][e]     = MASKV;
                    if (keyc + e > q0 + r0 + 8) s[nf][2 + e] = MASKV;
                }
            }
        }
        if (kb == kb_lo && qb >= 8) {
            #pragma unroll
            for (int nf = 0; nf < 4; nf++) {
                int keyc = k0 + wn * 32 + nf * 8 + (lane & 3) * 2;
                #pragma unroll
                for (int e = 0; e < 2; e++) {
                    if (keyc + e < q0 + r0 - (WIN - 1))     s[nf][e]     = MASKV;
                    if (keyc + e < q0 + r0 + 8 - (WIN - 1)) s[nf][2 + e] = MASKV;
                }
            }
        }

        // ---- row max (32 cols per warp, then cross-warp) ----
        float rm0 = -3.0e38f, rm1 = -3.0e38f;
        #pragma unroll
        for (int nf = 0; nf < 4; nf++) {
            rm0 = fmaxf(rm0, fmaxf(s[nf][0], s[nf][1]));
            rm1 = fmaxf(rm1, fmaxf(s[nf][2], s[nf][3]));
        }
        rm0 = fmaxf(rm0, __shfl_xor_sync(0xffffffffu, rm0, 1));
        rm0 = fmaxf(rm0, __shfl_xor_sync(0xffffffffu, rm0, 2));
        rm1 = fmaxf(rm1, __shfl_xor_sync(0xffffffffu, rm1, 1));
        rm1 = fmaxf(rm1, __shfl_xor_sync(0xffffffffu, rm1, 2));
        if ((lane & 3) == 0) {
            red_m[wn * 64 + r0]     = rm0;
            red_m[wn * 64 + r0 + 8] = rm1;
        }
        __syncthreads();

        float mo0 = sm_m[r0], mo1 = sm_m[r0 + 8];
        float mn0 = fmaxf(fmaxf(red_m[r0], red_m[64 + r0]), mo0);
        float mn1 = fmaxf(fmaxf(red_m[r0 + 8], red_m[64 + r0 + 8]), mo1);
        __syncthreads();  // everyone read sm_m before overwrite
        if (wn == 0 && (lane & 3) == 0) { sm_m[r0] = mn0; sm_m[r0 + 8] = mn1; }
        float alpha0 = __expf(mo0 - mn0);
        float alpha1 = __expf(mo1 - mn1);

        // ---- exp, row sums, P hi/lo to smem ----
        float ls0 = 0.0f, ls1 = 0.0f;
        #pragma unroll
        for (int nf = 0; nf < 4; nf++) {
            float p0 = __expf(s[nf][0] - mn0);
            float p1 = __expf(s[nf][1] - mn0);
            float p2 = __expf(s[nf][2] - mn1);
            float p3 = __expf(s[nf][3] - mn1);
            ls0 += p0 + p1;
            ls1 += p2 + p3;
            uint32_t colb2 = (uint32_t)((wn * 32 + nf * 8 + (lane & 3) * 2) * 2);
            __nv_bfloat16 h0 = __float2bfloat16(p0), h1 = __float2bfloat16(p1);
            __nv_bfloat16 h2 = __float2bfloat16(p2), h3 = __float2bfloat16(p3);
            *(__nv_bfloat162*)(smem + O_PH + r0 * 144 + colb2)       = __halves2bfloat162(h0, h1);
            *(__nv_bfloat162*)(smem + O_PH + (r0 + 8) * 144 + colb2) = __halves2bfloat162(h2, h3);
            *(__nv_bfloat162*)(smem + O_PL + r0 * 144 + colb2) =
                __halves2bfloat162(__float2bfloat16(p0 - __bfloat162float(h0)),
                                   __float2bfloat16(p1 - __bfloat162float(h1)));
            *(__nv_bfloat162*)(smem + O_PL + (r0 + 8) * 144 + colb2) =
                __halves2bfloat162(__float2bfloat16(p2 - __bfloat162float(h2)),
                                   __float2bfloat16(p3 - __bfloat162float(h3)));
        }
        ls0 += __shfl_xor_sync(0xffffffffu, ls0, 1);
        ls0 += __shfl_xor_sync(0xffffffffu, ls0, 2);
        ls1 += __shfl_xor_sync(0xffffffffu, ls1, 1);
        ls1 += __shfl_xor_sync(0xffffffffu, ls1, 2);
        if ((lane & 3) == 0) {
            red_s[wn * 64 + r0]     = ls0;
            red_s[wn * 64 + r0 + 8] = ls1;
        }

        // rescale O
        #pragma unroll
        for (int nf = 0; nf < 16; nf++) {
            acc_o[nf][0] *= alpha0;
            acc_o[nf][1] *= alpha0;
            acc_o[nf][2] *= alpha1;
            acc_o[nf][3] *= alpha1;
        }
        __syncthreads();  // P and red_s visible
        if (wn == 0 && (lane & 3) == 0) {
            sm_l[r0]     = sm_l[r0] * alpha0 + red_s[r0] + red_s[64 + r0];
            sm_l[r0 + 8] = sm_l[r0 + 8] * alpha1 + red_s[r0 + 8] + red_s[64 + r0 + 8];
        }

        // ---- O += P V (3-term) ----
        #pragma unroll
        for (int ks = 0; ks < 4; ks++) {
            uint32_t pah[4], pal[4];
            uint32_t paddr = (uint32_t)(arow * 144 + ks * 32) + acolx;
            ldm4(sb + O_PH + paddr, pah);
            ldm4(sb + O_PL + paddr, pal);
            #pragma unroll
            for (int ng = 0; ng < 8; ng++) {
                int vkrow = ks * 16 + (lane & 7) + (((lane >> 3) & 1) << 3);
                uint32_t vcolb = (uint32_t)((wn * 128 + ng * 16 + (((lane >> 4) & 1) << 3)) * 2);
                uint32_t vh[4], vl[4];
                ldm4t(sb + O_VH + SWZ(vkrow, vcolb), vh);
                ldm4t(sb + O_VL + SWZ(vkrow, vcolb), vl);
                mma16816(acc_o[ng * 2 + 0], pah, vh[0], vh[1]);
                mma16816(acc_o[ng * 2 + 1], pah, vh[2], vh[3]);
                mma16816(acc_o[ng * 2 + 0], pal, vh[0], vh[1]);
                mma16816(acc_o[ng * 2 + 1], pal, vh[2], vh[3]);
                mma16816(acc_o[ng * 2 + 0], pah, vl[0], vl[1]);
                mma16816(acc_o[ng * 2 + 1], pah, vl[2], vl[3]);
            }
        }
    }

    __syncthreads();
    const float inv0 = 1.0f / sm_l[r0];
    const float inv1 = 1.0f / sm_l[r0 + 8];
    const size_t tok0 = (size_t)(q0 + r0) * DIM + h * HDIM;
    const size_t tok1 = (size_t)(q0 + r0 + 8) * DIM + h * HDIM;
    #pragma unroll
    for (int nf = 0; nf < 16; nf++) {
        int col = wn * 128 + nf * 8 + (lane & 3) * 2;
        float v0 = acc_o[nf][0] * inv0, v1 = acc_o[nf][1] * inv0;
        float v2 = acc_o[nf][2] * inv1, v3 = acc_o[nf][3] * inv1;
        __nv_bfloat16 h0 = __float2bfloat16(v0), h1 = __float2bfloat16(v1);
        __nv_bfloat16 h2 = __float2bfloat16(v2), h3 = __float2bfloat16(v3);
        *(__nv_bfloat162*)(g_ah + tok0 + col) = __halves2bfloat162(h0, h1);
        *(__nv_bfloat162*)(g_ah + tok1 + col) = __halves2bfloat162(h2, h3);
        *(__nv_bfloat162*)(g_al + tok0 + col) =
            __halves2bfloat162(__float2bfloat16(v0 - __bfloat162float(h0)),
                               __float2bfloat16(v1 - __bfloat162float(h1)));
        *(__nv_bfloat162*)(g_al + tok1 + col) =
            __halves2bfloat162(__float2bfloat16(v2 - __bfloat162float(h2)),
                               __float2bfloat16(v3 - __bfloat162float(h3)));
    }
}

// ---------------------------------------------------------------------------
extern "C" void kernel_launch(void* const* d_in, const int* in_sizes, int n_in,
                              void* d_out, int out_size) {
    const float* x         = (const float*)d_in[0];
    const int*   positions = (const int*)d_in[1];
    const float* Wq        = (const float*)d_in[2];
    const float* Wk        = (const float*)d_in[3];
    const float* Wv        = (const float*)d_in[4];
    const float* Wo        = (const float*)d_in[5];
    const float* q_scale   = (const float*)d_in[6];
    const float* k_scale   = (const float*)d_in[7];
    float* out = (float*)d_out;

    float *qp, *kvp;
    cudaGetSymbolAddress((void**)&qp,  g_q);
    cudaGetSymbolAddress((void**)&kvp, g_kv);

    __nv_bfloat16 *xh, *xl, *ah, *al, *wqh, *wql, *wkvh, *wkvl, *woh, *wol;
    cudaGetSymbolAddress((void**)&xh, g_xh);     cudaGetSymbolAddress((void**)&xl, g_xl);
    cudaGetSymbolAddress((void**)&ah, g_ah);     cudaGetSymbolAddress((void**)&al, g_al);
    cudaGetSymbolAddress((void**)&wqh, g_wqh);   cudaGetSymbolAddress((void**)&wql, g_wql);
    cudaGetSymbolAddress((void**)&wkvh, g_wkvh); cudaGetSymbolAddress((void**)&wkvl, g_wkvl);
    cudaGetSymbolAddress((void**)&woh, g_woh);   cudaGetSymbolAddress((void**)&wol, g_wol);

    cudaFuncSetAttribute(gemm_mma3, cudaFuncAttributeMaxDynamicSharedMemorySize, GSMEM);
    cudaFuncSetAttribute(attn_mma, cudaFuncAttributeMaxDynamicSharedMemorySize, ATT2_SMEM);

    const int n4 = SL * DIM / 4;

    // split inputs
    split_kernel<<<n4 / 256, 256>>>(x, xh, xl, n4);
    splitT_kernel<<<dim3(DIM / 32, DIM / 32), dim3(32, 8)>>>(Wq, wqh, wql, DIM, DIM);
    splitT_kernel<<<dim3(KVD / 32, DIM / 32), dim3(32, 8)>>>(Wk, wkvh, wkvl, DIM, KVD);
    splitT_kernel<<<dim3(KVD / 32, DIM / 32), dim3(32, 8)>>>(Wv, wkvh + (size_t)KVD * DIM,
                                                             wkvl + (size_t)KVD * DIM, DIM, KVD);
    splitT_kernel<<<dim3(DIM / 32, DIM / 32), dim3(32, 8)>>>(Wo, woh, wol, DIM, DIM);

    // projections
    gemm_mma3<<<dim3(DIM / 128, SL / 128), 256, GSMEM>>>(xh, xl, wqh, wql, qp, DIM);
    gemm_mma3<<<dim3(KVS / 128, SL / 128), 256, GSMEM>>>(xh, xl, wkvh, wkvl, kvp, KVS);

    // RMSNorm + RoPE -> bf16 hi/lo
    norm_rope_kernel<<<dim3(SL, 12), 128>>>(positions, q_scale, k_scale);

    // tensor-core attention -> bf16 hi/lo att
    attn_mma<<<dim3(SL / 64, NH), 256, ATT2_SMEM>>>();

    // output projection
    gemm_mma3<<<dim3(DIM / 128, SL / 128), 256, GSMEM>>>(ah, al, woh, wol, out, DIM);
}

// round 12
// speedup vs baseline: 3.3048x; 1.4033x over previous
#include <cuda_runtime.h>
#include <cuda_fp16.h>
#include <math.h>
#include <stdint.h>

#define SL   4096
#define DIM  2048
#define NH   8
#define NKV  2
#define HDIM 256
#define WIN  512
#define KVD  512
#define QKVN 3072   // packed Q|K|V output width

// ---------------- scratch ----------------
__device__ float g_qkv[SL * QKVN];          // fp32 packed projection output
__device__ __half g_xh[SL * DIM],  g_xl[SL * DIM];
__device__ __half g_qh[SL * DIM],  g_ql[SL * DIM];
__device__ __half g_kh[SL * KVD],  g_kl[SL * KVD];
__device__ __half g_vh[SL * KVD];
__device__ __half g_ah[SL * DIM];
__device__ __half g_wh[QKVN * DIM], g_wl[QKVN * DIM];   // packed Wq|Wk|Wv (transposed)
__device__ __half g_woh[DIM * DIM];

__device__ __forceinline__ uint32_t smem_u32(const void* p) {
    uint32_t a;
    asm("{ .reg .u64 t; cvta.to.shared.u64 t, %1; cvt.u32.u64 %0, t; }" : "=r"(a) : "l"(p));
    return a;
}
__device__ __forceinline__ void cp16(uint32_t dst, const void* src) {
    asm volatile("cp.async.cg.shared.global [%0], [%1], 16;" :: "r"(dst), "l"(src) : "memory");
}
__device__ __forceinline__ void ldm4(uint32_t a, uint32_t r[4]) {
    asm volatile("ldmatrix.sync.aligned.m8n8.x4.shared.b16 {%0,%1,%2,%3}, [%4];"
                 : "=r"(r[0]), "=r"(r[1]), "=r"(r[2]), "=r"(r[3]) : "r"(a));
}
__device__ __forceinline__ void ldm4t(uint32_t a, uint32_t r[4]) {
    asm volatile("ldmatrix.sync.aligned.m8n8.x4.trans.shared.b16 {%0,%1,%2,%3}, [%4];"
                 : "=r"(r[0]), "=r"(r[1]), "=r"(r[2]), "=r"(r[3]) : "r"(a));
}
__device__ __forceinline__ void mma_h(float c[4], const uint32_t a[4], uint32_t b0, uint32_t b1) {
    asm volatile("mma.sync.aligned.m16n8k16.row.col.f32.f16.f16.f32 "
                 "{%0,%1,%2,%3}, {%4,%5,%6,%7}, {%8,%9}, {%0,%1,%2,%3};"
                 : "+f"(c[0]), "+f"(c[1]), "+f"(c[2]), "+f"(c[3])
                 : "r"(a[0]), "r"(a[1]), "r"(a[2]), "r"(a[3]), "r"(b0), "r"(b1));
}

// ---------------- conversion kernels ----------------
__global__ void split_kernel(const float* __restrict__ src,
                             __half* __restrict__ hi, __half* __restrict__ lo, int n4) {
    int i = blockIdx.x * blockDim.x + threadIdx.x;
    if (i >= n4) return;
    float4 v = ((const float4*)src)[i];
    float f[4] = {v.x, v.y, v.z, v.w};
    __half h[4], l[4];
    #pragma unroll
    for (int j = 0; j < 4; j++) {
        h[j] = __float2half(f[j]);
        l[j] = __float2half(f[j] - __half2float(h[j]));
    }
    __half2* h2 = (__half2*)hi;
    __half2* l2 = (__half2*)lo;
    h2[2 * i + 0] = __halves2half2(h[0], h[1]);
    h2[2 * i + 1] = __halves2half2(h[2], h[3]);
    l2[2 * i + 0] = __halves2half2(l[0], l[1]);
    l2[2 * i + 1] = __halves2half2(l[2], l[3]);
}

// src [K, N] fp32 -> hi/lo [N, K] fp16 (transposed)
template<bool WLO>
__global__ void splitT_kernel(const float* __restrict__ src,
                              __half* __restrict__ hi, __half* __restrict__ lo, int K, int N) {
    __shared__ float t[32][33];
    const int tx = threadIdx.x, ty = threadIdx.y;
    const int n0 = blockIdx.x * 32, k0 = blockIdx.y * 32;
    #pragma unroll
    for (int i = 0; i < 32; i += 8)
        t[ty + i][tx] = src[(size_t)(k0 + ty + i) * N + n0 + tx];
    __syncthreads();
    #pragma unroll
    for (int i = 0; i < 32; i += 8) {
        float v = t[tx][ty + i];
        __half h = __float2half(v);
        size_t o = (size_t)(n0 + ty + i) * K + k0 + tx;
        hi[o] = h;
        if (WLO) lo[o] = __float2half(v - __half2float(h));
    }
}

// ---------------- fp16 mma GEMM: C[M,N] = A[M,2048] @ B[N,2048]^T ----------------
// 128x256 block tile, 8 warps (2m x 4n, 64x64 each), K-chunk 64, 2-stage cp.async.
#define GBK 64

template<int TERMS>
__device__ __forceinline__ void gh_load(uint32_t st,
                                        const __half* __restrict__ Ah, const __half* __restrict__ Al,
                                        const __half* __restrict__ Bh, const __half* __restrict__ Bl,
                                        int m0, int n0, int kc) {
    constexpr int AOFFL = 18432;
    constexpr int BOFF  = (TERMS == 3) ? 36864 : 18432;
    constexpr int BOFFL = 73728;
    const int tid = threadIdx.x;
    #pragma unroll
    for (int it = 0; it < 4; it++) {
        int u = it * 256 + tid, row = u >> 3, cb = (u & 7) * 16;
        cp16(st + row * 144 + cb, (const char*)(Ah + (size_t)(m0 + row) * DIM + kc) + cb);
        if (TERMS == 3)
            cp16(st + AOFFL + row * 144 + cb, (const char*)(Al + (size_t)(m0 + row) * DIM + kc) + cb);
    }
    #pragma unroll
    for (int it = 0; it < 8; it++) {
        int u = it * 256 + tid, row = u >> 3, cb = (u & 7) * 16;
        cp16(st + BOFF + row * 144 + cb, (const char*)(Bh + (size_t)(n0 + row) * DIM + kc) + cb);
        if (TERMS == 3)
            cp16(st + BOFFL + row * 144 + cb, (const char*)(Bl + (size_t)(n0 + row) * DIM + kc) + cb);
    }
}

template<int TERMS>
__global__ __launch_bounds__(256, 1)
void gemm_h(const __half* __restrict__ Ah, const __half* __restrict__ Al,
            const __half* __restrict__ Bh, const __half* __restrict__ Bl,
            float* __restrict__ C, int Nld) {
    constexpr int AOFFL = 18432;
    constexpr int BOFF  = (TERMS == 3) ? 36864 : 18432;
    constexpr int BOFFL = 73728;
    constexpr int STG   = (TERMS == 3) ? 110592 : 55296;
    extern __shared__ char smem[];
    const uint32_t sb = smem_u32(smem);
    const int tid = threadIdx.x, lane = tid & 31, w = tid >> 5;
    const int wmi = w >> 2, wni = w & 3;
    const int m0 = blockIdx.y * 128, n0 = blockIdx.x * 256;

    uint32_t a_off[4], b_off[4];
    #pragma unroll
    for (int mi = 0; mi < 4; mi++)
        a_off[mi] = (uint32_t)((wmi * 64 + mi * 16 + (lane & 15)) * 144 + ((lane >> 4) << 4));
    #pragma unroll
    for (int ni = 0; ni < 4; ni++)
        b_off[ni] = (uint32_t)((wni * 64 + ni * 16 + (lane & 7) + ((lane >> 4) << 3)) * 144
                               + (((lane >> 3) & 1) << 4));

    float acc[4][8][4];
    #pragma unroll
    for (int mi = 0; mi < 4; mi++)
        #pragma unroll
        for (int nj = 0; nj < 8; nj++)
            #pragma unroll
            for (int e = 0; e < 4; e++) acc[mi][nj][e] = 0.0f;

    const int nch = DIM / GBK;   // 32

    gh_load<TERMS>(sb, Ah, Al, Bh, Bl, m0, n0, 0);
    asm volatile("cp.async.commit_group;" ::: "memory");
    gh_load<TERMS>(sb + STG, Ah, Al, Bh, Bl, m0, n0, GBK);
    asm volatile("cp.async.commit_group;" ::: "memory");

    for (int c = 0; c < nch; c++) {
        if (c == nch - 1) asm volatile("cp.async.wait_group 0;" ::: "memory");
        else              asm volatile("cp.async.wait_group 1;" ::: "memory");
        __syncthreads();

        const uint32_t st = sb + (uint32_t)(c & 1) * STG;

        #pragma unroll
        for (int ks = 0; ks < 4; ks++) {
            const uint32_t kb = (uint32_t)(ks * 32);
            uint32_t ah[4][4], bh[4][4];
            uint32_t al[4][4], bl[4][4];
            #pragma unroll
            for (int mi = 0; mi < 4; mi++) {
                ldm4(st + a_off[mi] + kb, ah[mi]);
                if (TERMS == 3) ldm4(st + AOFFL + a_off[mi] + kb, al[mi]);
            }
            #pragma unroll
            for (int ni = 0; ni < 4; ni++) {
                ldm4(st + BOFF + b_off[ni] + kb, bh[ni]);
                if (TERMS == 3) ldm4(st + BOFFL + b_off[ni] + kb, bl[ni]);
            }
            #pragma unroll
            for (int mi = 0; mi < 4; mi++)
                #pragma unroll
                for (int ni = 0; ni < 4; ni++) {
                    mma_h(acc[mi][ni * 2 + 0], ah[mi], bh[ni][0], bh[ni][1]);
                    mma_h(acc[mi][ni * 2 + 1], ah[mi], bh[ni][2], bh[ni][3]);
                    if (TERMS == 3) {
                        mma_h(acc[mi][ni * 2 + 0], al[mi], bh[ni][0], bh[ni][1]);
                        mma_h(acc[mi][ni * 2 + 1], al[mi], bh[ni][2], bh[ni][3]);
                        mma_h(acc[mi][ni * 2 + 0], ah[mi], bl[ni][0], bl[ni][1]);
                        mma_h(acc[mi][ni * 2 + 1], ah[mi], bl[ni][2], bl[ni][3]);
                    }
                }
        }
        __syncthreads();
        if (c + 2 < nch) {
            gh_load<TERMS>(sb + (uint32_t)(c & 1) * STG, Ah, Al, Bh, Bl, m0, n0, (c + 2) * GBK);
            asm volatile("cp.async.commit_group;" ::: "memory");
        }
    }

    const int mbase = m0 + wmi * 64 + (lane >> 2);
    const int nbase = n0 + wni * 64 + (lane & 3) * 2;
    #pragma unroll
    for (int mi = 0; mi < 4; mi++)
        #pragma unroll
        for (int nj = 0; nj < 8; nj++) {
            float* p0 = C + (size_t)(mbase + mi * 16) * Nld + nbase + nj * 8;
            float* p1 = C + (size_t)(mbase + mi * 16 + 8) * Nld + nbase + nj * 8;
            *(float2*)p0 = make_float2(acc[mi][nj][0], acc[mi][nj][1]);
            *(float2*)p1 = make_float2(acc[mi][nj][2], acc[mi][nj][3]);
        }
}

// ---------------- RMSNorm + RoPE -> fp16 hi/lo ----------------
__global__ void norm_rope_kernel(const int* __restrict__ positions,
                                 const float* __restrict__ q_scale,
                                 const float* __restrict__ k_scale) {
    const int token = blockIdx.x;
    const int which = blockIdx.y;
    const float* base;
    __half *oh, *ol = nullptr;
    const float* scale = nullptr;
    bool do_rope = true;
    if (which < 8) {
        base = g_qkv + (size_t)token * QKVN + which * HDIM;
        oh = g_qh + (size_t)token * DIM + which * HDIM;
        ol = g_ql + (size_t)token * DIM + which * HDIM;
        scale = q_scale;
    } else if (which < 10) {
        base = g_qkv + (size_t)token * QKVN + 2048 + (which - 8) * HDIM;
        oh = g_kh + (size_t)token * KVD + (which - 8) * HDIM;
        ol = g_kl + (size_t)token * KVD + (which - 8) * HDIM;
        scale = k_scale;
    } else {
        base = g_qkv + (size_t)token * QKVN + 2560 + (which - 10) * HDIM;
        oh = g_vh + (size_t)token * KVD + (which - 10) * HDIM;
        do_rope = false;
    }

    const int t = threadIdx.x;
    float x1 = base[t];
    float x2 = base[t + 128];

    float ss = x1 * x1 + x2 * x2;
    #pragma unroll
    for (int off = 16; off > 0; off >>= 1)
        ss += __shfl_xor_sync(0xffffffffu, ss, off);
    __shared__ float red[4];
    if ((t & 31) == 0) red[t >> 5] = ss;
    __syncthreads();
    ss = red[0] + red[1] + red[2] + red[3];

    float inv = rsqrtf(ss * (1.0f / 256.0f) + 1e-6f);
    x1 *= inv;
    x2 *= inv;
    if (scale) { x1 *= scale[t]; x2 *= scale[t + 128]; }

    float y1, y2;
    if (do_rope) {
        float pos = (float)positions[token];
        float timescale = powf(10000.0f, (float)t * (1.0f / 128.0f));
        float sinu = pos / timescale;
        float sv, cv;
        sincosf(sinu, &sv, &cv);
        y1 = x1 * cv - x2 * sv;
        y2 = x2 * cv + x1 * sv;
    } else {
        y1 = x1; y2 = x2;
    }
    __half h1 = __float2half(y1);
    __half h2 = __float2half(y2);
    oh[t] = h1;
    oh[t + 128] = h2;
    if (ol) {
        ol[t]       = __float2half(y1 - __half2float(h1));
        ol[t + 128] = __float2half(y2 - __half2float(h2));
    }
}

// ---------------- tensor-core sliding-window attention (fp16) ----------------
// 64q x 64k tiles; QK 3-term, PV 1-term.
#define SWZ(row, colb) ((uint32_t)((row) * 512 + ((colb) ^ (((row) & 7) << 4))))
#define O_QH 0
#define O_QL 32768
#define O_KH 65536
#define O_KL 98304
#define O_VH 131072
#define O_PH 163840
#define O_SM  (O_PH + 9216)
#define O_SLN (O_SM + 256)
#define O_RM  (O_SLN + 256)
#define O_RS  (O_RM + 512)
#define ATT2_SMEM (O_RS + 512)
#define MASKV (-10000.0f)

__global__ __launch_bounds__(256, 1)
void attn_mma() {
    extern __shared__ char smem[];
    const uint32_t sb = smem_u32(smem);
    const int tid = threadIdx.x, lane = tid & 31, w = tid >> 5;
    const int wm = w & 3, wn = w >> 2;
    const int qb = blockIdx.x, q0 = qb << 6;
    const int h = blockIdx.y, khd = h >> 2;

    float* sm_m = (float*)(smem + O_SM);
    float* sm_l = (float*)(smem + O_SLN);
    float* red_m = (float*)(smem + O_RM);
    float* red_s = (float*)(smem + O_RS);

    if (tid < 64) { sm_m[tid] = MASKV; sm_l[tid] = 0.0f; }

    // load Q hi/lo (once)
    {
        const __half* qh = g_qh + (size_t)q0 * DIM + h * HDIM;
        const __half* ql = g_ql + (size_t)q0 * DIM + h * HDIM;
        #pragma unroll
        for (int it = 0; it < 8; it++) {
            int u = it * 256 + tid, row = u >> 5, colb = (u & 31) * 16;
            uint32_t swo = SWZ(row, colb);
            cp16(sb + O_QH + swo, (const char*)(qh + (size_t)row * DIM) + colb);
            cp16(sb + O_QL + swo, (const char*)(ql + (size_t)row * DIM) + colb);
        }
    }
    asm volatile("cp.async.commit_group;" ::: "memory");

    const int arow = wm * 16 + (lane & 15);
    const uint32_t acolx = (uint32_t)((lane >> 4) << 4);
    const int r0 = wm * 16 + (lane >> 2);

    float acc_o[16][4];
    #pragma unroll
    for (int nf = 0; nf < 16; nf++)
        #pragma unroll
        for (int e = 0; e < 4; e++) acc_o[nf][e] = 0.0f;

    const int kb_lo = (qb >= 8) ? qb - 8 : 0;

    for (int kb = kb_lo; kb <= qb; kb++) {
        const int k0 = kb << 6;
        __syncthreads();

        // load K hi/lo + V hi for this chunk
        #pragma unroll
        for (int it = 0; it < 8; it++) {
            int u = it * 256 + tid, row = u >> 5, colb = (u & 31) * 16;
            size_t gro = (size_t)(k0 + row) * KVD + khd * HDIM;
            uint32_t swo = SWZ(row, colb);
            cp16(sb + O_KH + swo, (const char*)(g_kh + gro) + colb);
            cp16(sb + O_KL + swo, (const char*)(g_kl + gro) + colb);
            cp16(sb + O_VH + swo, (const char*)(g_vh + gro) + colb);
        }
        asm volatile("cp.async.commit_group;" ::: "memory");
        asm volatile("cp.async.wait_group 0;" ::: "memory");
        __syncthreads();

        // ---- scores: S = Q K^T (3-term) ----
        float s[4][4];
        #pragma unroll
        for (int nf = 0; nf < 4; nf++)
            #pragma unroll
            for (int e = 0; e < 4; e++) s[nf][e] = 0.0f;

        #pragma unroll
        for (int ks = 0; ks < 16; ks++) {
            uint32_t ah[4], al_[4];
            ldm4(sb + O_QH + SWZ(arow, ks * 32 + acolx), ah);
            ldm4(sb + O_QL + SWZ(arow, ks * 32 + acolx), al_);
            #pragma unroll
            for (int ni = 0; ni < 2; ni++) {
                int brow = wn * 32 + ni * 16 + (lane & 7) + ((lane >> 4) << 3);
                uint32_t bcolb = (uint32_t)(ks * 32 + (((lane >> 3) & 1) << 4));
                uint32_t bh[4], bl[4];
                ldm4(sb + O_KH + SWZ(brow, bcolb), bh);
                ldm4(sb + O_KL + SWZ(brow, bcolb), bl);
                mma_h(s[ni * 2 + 0], ah, bh[0], bh[1]);
                mma_h(s[ni * 2 + 1], ah, bh[2], bh[3]);
                mma_h(s[ni * 2 + 0], al_, bh[0], bh[1]);
                mma_h(s[ni * 2 + 1], al_, bh[2], bh[3]);
                mma_h(s[ni * 2 + 0], ah, bl[0], bl[1]);
                mma_h(s[ni * 2 + 1], ah, bl[2], bl[3]);
            }
        }

        // ---- masking ----
        if (kb == qb) {
            #pragma unroll
            for (int nf = 0; nf < 4; nf++) {
                int keyc = k0 + wn * 32 + nf * 8 + (lane & 3) * 2;
                #pragma unroll
                for (int e = 0; e < 2; e++) {
                    if (keyc + e > q0 + r0)     s[nf][e]     = MASKV;
                    if (keyc + e > q0 + r0 + 8) s[nf][2 + e] = MASKV;
                }
            }
        }
        if (kb == kb_lo && qb >= 8) {
            #pragma unroll
            for (int nf = 0; nf < 4; nf++) {
                int keyc = k0 + wn * 32 + nf * 8 + (lane & 3) * 2;
                #pragma unroll
                for (int e = 0; e < 2; e++) {
                    if (keyc + e < q0 + r0 - (WIN - 1))     s[nf][e]     = MASKV;
                    if (keyc + e < q0 + r0 + 8 - (WIN - 1)) s[nf][2 + e] = MASKV;
                }
            }
        }

        // ---- row max ----
        float rm0 = -3.0e38f, rm1 = -3.0e38f;
        #pragma unroll
        for (int nf = 0; nf < 4; nf++) {
            rm0 = fmaxf(rm0, fmaxf(s[nf][0], s[nf][1]));
            rm1 = fmaxf(rm1, fmaxf(s[nf][2], s[nf][3]));
        }
        rm0 = fmaxf(rm0, __shfl_xor_sync(0xffffffffu, rm0, 1));
        rm0 = fmaxf(rm0, __shfl_xor_sync(0xffffffffu, rm0, 2));
        rm1 = fmaxf(rm1, __shfl_xor_sync(0xffffffffu, rm1, 1));
        rm1 = fmaxf(rm1, __shfl_xor_sync(0xffffffffu, rm1, 2));
        if ((lane & 3) == 0) {
            red_m[wn * 64 + r0]     = rm0;
            red_m[wn * 64 + r0 + 8] = rm1;
        }
        __syncthreads();

        float mo0 = sm_m[r0], mo1 = sm_m[r0 + 8];
        float mn0 = fmaxf(fmaxf(red_m[r0], red_m[64 + r0]), mo0);
        float mn1 = fmaxf(fmaxf(red_m[r0 + 8], red_m[64 + r0 + 8]), mo1);
        __syncthreads();
        if (wn == 0 && (lane & 3) == 0) { sm_m[r0] = mn0; sm_m[r0 + 8] = mn1; }
        float alpha0 = __expf(mo0 - mn0);
        float alpha1 = __expf(mo1 - mn1);

        // ---- exp, row sums, P (hi only) ----
        float ls0 = 0.0f, ls1 = 0.0f;
        #pragma unroll
        for (int nf = 0; nf < 4; nf++) {
            float p0 = __expf(s[nf][0] - mn0);
            float p1 = __expf(s[nf][1] - mn0);
            float p2 = __expf(s[nf][2] - mn1);
            float p3 = __expf(s[nf][3] - mn1);
            ls0 += p0 + p1;
            ls1 += p2 + p3;
            uint32_t colb2 = (uint32_t)((wn * 32 + nf * 8 + (lane & 3) * 2) * 2);
            *(__half2*)(smem + O_PH + r0 * 144 + colb2) =
                __halves2half2(__float2half(p0), __float2half(p1));
            *(__half2*)(smem + O_PH + (r0 + 8) * 144 + colb2) =
                __halves2half2(__float2half(p2), __float2half(p3));
        }
        ls0 += __shfl_xor_sync(0xffffffffu, ls0, 1);
        ls0 += __shfl_xor_sync(0xffffffffu, ls0, 2);
        ls1 += __shfl_xor_sync(0xffffffffu, ls1, 1);
        ls1 += __shfl_xor_sync(0xffffffffu, ls1, 2);
        if ((lane & 3) == 0) {
            red_s[wn * 64 + r0]     = ls0;
            red_s[wn * 64 + r0 + 8] = ls1;
        }

        #pragma unroll
        for (int nf = 0; nf < 16; nf++) {
            acc_o[nf][0] *= alpha0;
            acc_o[nf][1] *= alpha0;
            acc_o[nf][2] *= alpha1;
            acc_o[nf][3] *= alpha1;
        }
        __syncthreads();
        if (wn == 0 && (lane & 3) == 0) {
            sm_l[r0]     = sm_l[r0] * alpha0 + red_s[r0] + red_s[64 + r0];
            sm_l[r0 + 8] = sm_l[r0 + 8] * alpha1 + red_s[r0 + 8] + red_s[64 + r0 + 8];
        }

        // ---- O += P V (1-term) ----
        #pragma unroll
        for (int ks = 0; ks < 4; ks++) {
            uint32_t pah[4];
            ldm4(sb + O_PH + (uint32_t)(arow * 144 + ks * 32) + acolx, pah);
            #pragma unroll
            for (int ng = 0; ng < 8; ng++) {
                int vkrow = ks * 16 + (lane & 7) + (((lane >> 3) & 1) << 3);
                uint32_t vcolb = (uint32_t)((wn * 128 + ng * 16 + (((lane >> 4) & 1) << 3)) * 2);
                uint32_t vh[4];
                ldm4t(sb + O_VH + SWZ(vkrow, vcolb), vh);
                mma_h(acc_o[ng * 2 + 0], pah, vh[0], vh[1]);
                mma_h(acc_o[ng * 2 + 1], pah, vh[2], vh[3]);
            }
        }
    }

    __syncthreads();
    const float inv0 = 1.0f / sm_l[r0];
    const float inv1 = 1.0f / sm_l[r0 + 8];
    const size_t tok0 = (size_t)(q0 + r0) * DIM + h * HDIM;
    const size_t tok1 = (size_t)(q0 + r0 + 8) * DIM + h * HDIM;
    #pragma unroll
    for (int nf = 0; nf < 16; nf++) {
        int col = wn * 128 + nf * 8 + (lane & 3) * 2;
        *(__half2*)(g_ah + tok0 + col) =
            __halves2half2(__float2half(acc_o[nf][0] * inv0), __float2half(acc_o[nf][1] * inv0));
        *(__half2*)(g_ah + tok1 + col) =
            __halves2half2(__float2half(acc_o[nf][2] * inv1), __float2half(acc_o[nf][3] * inv1));
    }
}

// ---------------------------------------------------------------------------
extern "C" void kernel_launch(void* const* d_in, const int* in_sizes, int n_in,
                              void* d_out, int out_size) {
    const float* x         = (const float*)d_in[0];
    const int*   positions = (const int*)d_in[1];
    const float* Wq        = (const float*)d_in[2];
    const float* Wk        = (const float*)d_in[3];
    const float* Wv        = (const float*)d_in[4];
    const float* Wo        = (const float*)d_in[5];
    const float* q_scale   = (const float*)d_in[6];
    const float* k_scale   = (const float*)d_in[7];
    float* out = (float*)d_out;

    float* qkvp;
    cudaGetSymbolAddress((void**)&qkvp, g_qkv);
    __half *xh, *xl, *ah, *wh, *wl, *woh;
    cudaGetSymbolAddress((void**)&xh, g_xh);
    cudaGetSymbolAddress((void**)&xl, g_xl);
    cudaGetSymbolAddress((void**)&ah, g_ah);
    cudaGetSymbolAddress((void**)&wh, g_wh);
    cudaGetSymbolAddress((void**)&wl, g_wl);
    cudaGetSymbolAddress((void**)&woh, g_woh);

    cudaFuncSetAttribute(gemm_h<3>, cudaFuncAttributeMaxDynamicSharedMemorySize, 2 * 110592);
    cudaFuncSetAttribute(gemm_h<1>, cudaFuncAttributeMaxDynamicSharedMemorySize, 2 * 55296);
    cudaFuncSetAttribute(attn_mma, cudaFuncAttributeMaxDynamicSharedMemorySize, ATT2_SMEM);

    const int n4 = SL * DIM / 4;

    // splits
    split_kernel<<<n4 / 256, 256>>>(x, xh, xl, n4);
    splitT_kernel<true><<<dim3(DIM / 32, DIM / 32), dim3(32, 8)>>>(Wq, wh, wl, DIM, DIM);
    splitT_kernel<true><<<dim3(KVD / 32, DIM / 32), dim3(32, 8)>>>(
        Wk, wh + (size_t)2048 * DIM, wl + (size_t)2048 * DIM, DIM, KVD);
    splitT_kernel<true><<<dim3(KVD / 32, DIM / 32), dim3(32, 8)>>>(
        Wv, wh + (size_t)2560 * DIM, wl + (size_t)2560 * DIM, DIM, KVD);
    splitT_kernel<false><<<dim3(DIM / 32, DIM / 32), dim3(32, 8)>>>(Wo, woh, nullptr, DIM, DIM);

    // fused QKV projection (3-term fp16)
    gemm_h<3><<<dim3(QKVN / 256, SL / 128), 256, 2 * 110592>>>(xh, xl, wh, wl, qkvp, QKVN);

    // RMSNorm + RoPE -> fp16 hi/lo
    norm_rope_kernel<<<dim3(SL, 12), 128>>>(positions, q_scale, k_scale);

    // attention (QK 3-term, PV 1-term)
    attn_mma<<<dim3(SL / 64, NH), 256, ATT2_SMEM>>>();

    // output projection (1-term fp16)
    gemm_h<1><<<dim3(DIM / 256, SL / 128), 256, 2 * 55296>>>(ah, nullptr, woh, nullptr, out, DIM);
}